// round 6
// baseline (speedup 1.0000x reference)
#include <cuda_runtime.h>
#include <cuda_fp16.h>
#include <math.h>
#include <stdint.h>

#define N_NODES 50000
#define N_EDGES 800000
#define IN_F 256
#define HID 128
#define OUT_F 8
#define N_GRAPHS 256
#define NEG_SLOPE 0.2f
#define NEG_BIG -1e30f

// ---------------- scratch (static device globals; no runtime alloc) ----------
__device__ int    g_is64;
__device__ int    g_deg[N_NODES];
__device__ int    g_rowptr[N_NODES + 1];
__device__ int    g_cursor[N_NODES];
__device__ int    g_csrc[N_EDGES];           // edge sources sorted by dst
__device__ int    g_bsum[64];
__device__ __half g_h[N_NODES * HID];        // GEMM output, fp16 (gather payload)
__device__ float  g_out[N_NODES * HID];      // aggregation output / next input
__device__ float  g_as[N_NODES];
__device__ float  g_ad[N_NODES];
__device__ float  g_pool[N_GRAPHS * HID];
__device__ int    g_cnt[N_GRAPHS];

// ---------------- utility kernels -------------------------------------------
__global__ void zero_i(int* p, int n) {
    int i = blockIdx.x * blockDim.x + threadIdx.x;
    if (i < n) p[i] = 0;
}
__global__ void zero_pool_kernel() {
    int i = blockIdx.x * blockDim.x + threadIdx.x;
    if (i < N_GRAPHS * HID) g_pool[i] = 0.0f;
    if (i < N_GRAPHS) g_cnt[i] = 0;
}

// Parallel int64-vs-int32 detection: all sampled high words zero => int64.
__global__ void detect_kernel(const unsigned* buf) {
    int i = threadIdx.x;                       // 256 threads
    int ok = (buf[2 * (i * 3001) + 1] == 0u) ? 1 : 0;
    int all = __syncthreads_and(ok);
    if (i == 0) g_is64 = all;
}

// destination histogram straight off the input buffer
__global__ void hist_kernel(const void* buf, int E) {
    int e = blockIdx.x * blockDim.x + threadIdx.x;
    if (e >= E) return;
    int d = g_is64 ? (int)((const long long*)buf)[E + e]
                   : ((const int*)buf)[E + e];
    atomicAdd(&g_deg[d], 1);
}

// ---------------- hierarchical CSR scan --------------------------------------
__global__ void scan1_kernel() {
    __shared__ int sh[1024];
    int b = blockIdx.x, tid = threadIdx.x;
    int idx = b * 1024 + tid;
    int v = (idx < N_NODES) ? g_deg[idx] : 0;
    sh[tid] = v;
    __syncthreads();
    for (int off = 1; off < 1024; off <<= 1) {
        int t = (tid >= off) ? sh[tid - off] : 0;
        __syncthreads();
        sh[tid] += t;
        __syncthreads();
    }
    if (idx < N_NODES) g_rowptr[idx] = sh[tid] - v;
    if (tid == 1023) g_bsum[b] = sh[1023];
}

#define N_SCAN_BLOCKS ((N_NODES + 1023) / 1024)   // 49
__global__ void scan2_kernel() {
    __shared__ int sh[64];
    int tid = threadIdx.x;
    int v = (tid < N_SCAN_BLOCKS) ? g_bsum[tid] : 0;
    sh[tid] = v;
    __syncthreads();
    for (int off = 1; off < 64; off <<= 1) {
        int t = (tid >= off) ? sh[tid - off] : 0;
        __syncthreads();
        sh[tid] += t;
        __syncthreads();
    }
    if (tid < N_SCAN_BLOCKS) g_bsum[tid] = sh[tid] - v;   // exclusive
    if (tid == N_SCAN_BLOCKS - 1) g_rowptr[N_NODES] = sh[tid];
}
__global__ void scan3_kernel() {
    int i = blockIdx.x * blockDim.x + threadIdx.x;
    if (i >= N_NODES) return;
    int r = g_rowptr[i] + g_bsum[i >> 10];
    g_rowptr[i] = r;
    g_cursor[i] = r;
}

__global__ void scatter_kernel(const void* buf, int E) {
    int e = blockIdx.x * blockDim.x + threadIdx.x;
    if (e >= E) return;
    int s, d;
    if (g_is64) {
        const long long* p = (const long long*)buf;
        s = (int)p[e];  d = (int)p[E + e];
    } else {
        const int* p = (const int*)buf;
        s = p[e];  d = p[E + e];
    }
    int pos = atomicAdd(&g_cursor[d], 1);
    g_csrc[pos] = s;
}

// --------- fp16 tensor-core GEMM + fused alpha epilogue ----------------------
// H[M,128](fp16) = A[M,K] @ W[K,128];  g_as/g_ad[row] = H_row . a_src / a_dst
#define BM 128
#define BN 128
#define BK 32
#define TS 40     // padded smem stride in halves: banks (20*r + tg) mod 32 distinct

__device__ __forceinline__ void mma_f16(float c[4], const uint32_t a[4],
                                        uint32_t b0, uint32_t b1) {
    asm volatile(
        "mma.sync.aligned.m16n8k16.row.col.f32.f16.f16.f32 "
        "{%0,%1,%2,%3}, {%4,%5,%6,%7}, {%8,%9}, {%0,%1,%2,%3};\n"
        : "+f"(c[0]), "+f"(c[1]), "+f"(c[2]), "+f"(c[3])
        : "r"(a[0]), "r"(a[1]), "r"(a[2]), "r"(a[3]), "r"(b0), "r"(b1));
}

__global__ __launch_bounds__(256) void gemm_f16_kernel(
    const float* __restrict__ A, const float* __restrict__ W,
    __half* __restrict__ C,
    const float* __restrict__ asrc, const float* __restrict__ adst,
    int M, int K)
{
    __shared__ __half As[BM][TS];
    __shared__ __half Ws[BN][TS];        // transposed: [n][k]
    __shared__ float sAs[BM][2];
    __shared__ float sAd[BM][2];

    int tid = threadIdx.x;
    int lane = tid & 31, warp = tid >> 5;
    int warpRow = warp >> 1, warpCol = warp & 1;   // 4 x 2 warps, tile 32x64
    int block_row = blockIdx.x * BM;
    int g = lane >> 2, tg = lane & 3;

    float c[2][8][4];
#pragma unroll
    for (int mi = 0; mi < 2; mi++)
#pragma unroll
        for (int ni = 0; ni < 8; ni++)
#pragma unroll
            for (int r = 0; r < 4; r++) c[mi][ni][r] = 0.0f;

    float4 aReg[4], wReg[4];
    // prefetch tile 0
#pragma unroll
    for (int i = 0; i < 4; i++) {
        int q = tid + i * 256;
        int row = q >> 3, c4 = q & 7;
        int gm = block_row + row;
        aReg[i] = make_float4(0, 0, 0, 0);
        if (gm < M) aReg[i] = *(const float4*)&A[(size_t)gm * K + c4 * 4];
        int k = q >> 5, n4 = q & 31;
        wReg[i] = *(const float4*)&W[(size_t)k * BN + n4 * 4];
    }

    for (int k0 = 0; k0 < K; k0 += BK) {
        // store prefetched tile (fp16-converted); W transposed to [n][k]
#pragma unroll
        for (int i = 0; i < 4; i++) {
            int q = tid + i * 256;
            int row = q >> 3, c4 = q & 7;
            *(__half2*)&As[row][c4 * 4]     = __floats2half2_rn(aReg[i].x, aReg[i].y);
            *(__half2*)&As[row][c4 * 4 + 2] = __floats2half2_rn(aReg[i].z, aReg[i].w);
            int k = q >> 5, n4 = q & 31;
            Ws[n4 * 4 + 0][k] = __float2half(wReg[i].x);
            Ws[n4 * 4 + 1][k] = __float2half(wReg[i].y);
            Ws[n4 * 4 + 2][k] = __float2half(wReg[i].z);
            Ws[n4 * 4 + 3][k] = __float2half(wReg[i].w);
        }
        __syncthreads();
        // prefetch next tile (overlaps MMA)
        if (k0 + BK < K) {
#pragma unroll
            for (int i = 0; i < 4; i++) {
                int q = tid + i * 256;
                int row = q >> 3, c4 = q & 7;
                int gm = block_row + row;
                aReg[i] = make_float4(0, 0, 0, 0);
                if (gm < M) aReg[i] = *(const float4*)&A[(size_t)gm * K + k0 + BK + c4 * 4];
                int k = q >> 5, n4 = q & 31;
                wReg[i] = *(const float4*)&W[(size_t)(k0 + BK + k) * BN + n4 * 4];
            }
        }
#pragma unroll
        for (int ks = 0; ks < BK; ks += 16) {
            uint32_t a[2][4];
#pragma unroll
            for (int mi = 0; mi < 2; mi++) {
                int r = warpRow * 32 + mi * 16;
                a[mi][0] = *(const uint32_t*)&As[r + g][ks + 2 * tg];
                a[mi][1] = *(const uint32_t*)&As[r + 8 + g][ks + 2 * tg];
                a[mi][2] = *(const uint32_t*)&As[r + g][ks + 2 * tg + 8];
                a[mi][3] = *(const uint32_t*)&As[r + 8 + g][ks + 2 * tg + 8];
            }
#pragma unroll
            for (int ni = 0; ni < 8; ni++) {
                int n = warpCol * 64 + ni * 8 + g;
                uint32_t b0 = *(const uint32_t*)&Ws[n][ks + 2 * tg];
                uint32_t b1 = *(const uint32_t*)&Ws[n][ks + 2 * tg + 8];
                mma_f16(c[0][ni], a[0], b0, b1);
                mma_f16(c[1][ni], a[1], b0, b1);
            }
        }
        __syncthreads();
    }

    // ---- epilogue 1: write fp16 H ----
#pragma unroll
    for (int mi = 0; mi < 2; mi++) {
#pragma unroll
        for (int ni = 0; ni < 8; ni++) {
            int r0 = block_row + warpRow * 32 + mi * 16 + g;
            int col = warpCol * 64 + ni * 8 + tg * 2;
            if (r0 < M)
                *(__half2*)&C[(size_t)r0 * 128 + col] =
                    __floats2half2_rn(c[mi][ni][0], c[mi][ni][1]);
            int r1 = r0 + 8;
            if (r1 < M)
                *(__half2*)&C[(size_t)r1 * 128 + col] =
                    __floats2half2_rn(c[mi][ni][2], c[mi][ni][3]);
        }
    }

    // ---- epilogue 2: fused alpha (h.a_src, h.a_dst) from fp32 accumulators --
    float pas[4] = {0, 0, 0, 0}, pad[4] = {0, 0, 0, 0};
#pragma unroll
    for (int ni = 0; ni < 8; ni++) {
        int col0 = warpCol * 64 + ni * 8 + tg * 2;
        float s0 = asrc[col0], s1 = asrc[col0 + 1];
        float d0 = adst[col0], d1 = adst[col0 + 1];
        pas[0] += c[0][ni][0] * s0 + c[0][ni][1] * s1;
        pas[1] += c[0][ni][2] * s0 + c[0][ni][3] * s1;
        pas[2] += c[1][ni][0] * s0 + c[1][ni][1] * s1;
        pas[3] += c[1][ni][2] * s0 + c[1][ni][3] * s1;
        pad[0] += c[0][ni][0] * d0 + c[0][ni][1] * d1;
        pad[1] += c[0][ni][2] * d0 + c[0][ni][3] * d1;
        pad[2] += c[1][ni][0] * d0 + c[1][ni][1] * d1;
        pad[3] += c[1][ni][2] * d0 + c[1][ni][3] * d1;
    }
#pragma unroll
    for (int o = 1; o <= 2; o <<= 1) {
#pragma unroll
        for (int r = 0; r < 4; r++) {
            pas[r] += __shfl_xor_sync(0xffffffffu, pas[r], o);
            pad[r] += __shfl_xor_sync(0xffffffffu, pad[r], o);
        }
    }
    if (tg == 0) {
        int lr = warpRow * 32 + g;
        sAs[lr][warpCol]      = pas[0];  sAd[lr][warpCol]      = pad[0];
        sAs[lr + 8][warpCol]  = pas[1];  sAd[lr + 8][warpCol]  = pad[1];
        sAs[lr + 16][warpCol] = pas[2];  sAd[lr + 16][warpCol] = pad[2];
        sAs[lr + 24][warpCol] = pas[3];  sAd[lr + 24][warpCol] = pad[3];
    }
    __syncthreads();
    if (tid < BM) {
        int gm = block_row + tid;
        if (gm < M) {
            g_as[gm] = sAs[tid][0] + sAs[tid][1];
            g_ad[gm] = sAd[tid][0] + sAd[tid][1];
        }
    }
}

// ---------------- edge aggregation (warp per destination node) ---------------
__device__ __forceinline__ float lrelu(float x) {
    return x > 0.0f ? x : NEG_SLOPE * x;
}

__global__ __launch_bounds__(256) void agg_kernel(
    const __half* __restrict__ H, const float* __restrict__ bias,
    float* __restrict__ Out, int do_relu)
{
    int warp = (blockIdx.x * blockDim.x + threadIdx.x) >> 5;
    int lane = threadIdx.x & 31;
    if (warp >= N_NODES) return;
    int beg = g_rowptr[warp], end = g_rowptr[warp + 1];
    float ad = g_ad[warp];

    // single pass online softmax; FINITE sentinel so empty-lane merges stay 0.
    float m = NEG_BIG, s = 0.0f;
    for (int i = beg + lane; i < end; i += 32) {
        float l = lrelu(g_as[g_csrc[i]] + ad);
        float nm = fmaxf(m, l);
        s = s * __expf(m - nm) + __expf(l - nm);
        m = nm;
    }
#pragma unroll
    for (int o = 16; o; o >>= 1) {
        float mo = __shfl_xor_sync(0xffffffffu, m, o);
        float so = __shfl_xor_sync(0xffffffffu, s, o);
        float nm = fmaxf(m, mo);
        s = s * __expf(m - nm) + so * __expf(mo - nm);
        m = nm;
    }
    float inv = (end > beg) ? 1.0f / s : 0.0f;

    // weighted feature accumulation (fp16 rows), unroll x2 for MLP
    float4 acc0 = make_float4(0, 0, 0, 0);
    float4 acc1 = make_float4(0, 0, 0, 0);
    int i = beg;
    for (; i + 1 < end; i += 2) {
        int s0 = g_csrc[i], s1 = g_csrc[i + 1];
        float w0 = __expf(lrelu(g_as[s0] + ad) - m) * inv;
        float w1 = __expf(lrelu(g_as[s1] + ad) - m) * inv;
        uint2 r0 = *(const uint2*)&H[(size_t)s0 * 128 + lane * 4];
        uint2 r1 = *(const uint2*)&H[(size_t)s1 * 128 + lane * 4];
        float2 a01 = __half22float2(*(const __half2*)&r0.x);
        float2 a23 = __half22float2(*(const __half2*)&r0.y);
        float2 b01 = __half22float2(*(const __half2*)&r1.x);
        float2 b23 = __half22float2(*(const __half2*)&r1.y);
        acc0.x = fmaf(w0, a01.x, acc0.x); acc0.y = fmaf(w0, a01.y, acc0.y);
        acc0.z = fmaf(w0, a23.x, acc0.z); acc0.w = fmaf(w0, a23.y, acc0.w);
        acc1.x = fmaf(w1, b01.x, acc1.x); acc1.y = fmaf(w1, b01.y, acc1.y);
        acc1.z = fmaf(w1, b23.x, acc1.z); acc1.w = fmaf(w1, b23.y, acc1.w);
    }
    if (i < end) {
        int s0 = g_csrc[i];
        float w0 = __expf(lrelu(g_as[s0] + ad) - m) * inv;
        uint2 r0 = *(const uint2*)&H[(size_t)s0 * 128 + lane * 4];
        float2 a01 = __half22float2(*(const __half2*)&r0.x);
        float2 a23 = __half22float2(*(const __half2*)&r0.y);
        acc0.x = fmaf(w0, a01.x, acc0.x); acc0.y = fmaf(w0, a01.y, acc0.y);
        acc0.z = fmaf(w0, a23.x, acc0.z); acc0.w = fmaf(w0, a23.y, acc0.w);
    }
    float4 acc = make_float4(acc0.x + acc1.x, acc0.y + acc1.y,
                             acc0.z + acc1.z, acc0.w + acc1.w);
    float4 bv = *(const float4*)&bias[lane * 4];
    acc.x += bv.x; acc.y += bv.y; acc.z += bv.z; acc.w += bv.w;
    if (do_relu) {
        acc.x = fmaxf(acc.x, 0.0f); acc.y = fmaxf(acc.y, 0.0f);
        acc.z = fmaxf(acc.z, 0.0f); acc.w = fmaxf(acc.w, 0.0f);
    }
    *(float4*)&Out[(size_t)warp * 128 + lane * 4] = acc;
}

// ---------------- pooling (batch is sorted -> run-length segmented) ----------
#define NODES_PER_BLOCK 64
__global__ void pool_kernel(const float* __restrict__ H, const void* __restrict__ batchbuf) {
    int tid = threadIdx.x;   // 128 = channel
    int n0 = blockIdx.x * NODES_PER_BLOCK;
    if (n0 >= N_NODES) return;
    int n1 = min(n0 + NODES_PER_BLOCK, N_NODES);
    int is64 = g_is64;
    const long long* b64 = (const long long*)batchbuf;
    const int* b32 = (const int*)batchbuf;
    int cur = is64 ? (int)b64[n0] : b32[n0];
    float acc = 0.0f;
    int run = 0;
    for (int n = n0; n < n1; n++) {
        int gg = is64 ? (int)b64[n] : b32[n];
        if (gg != cur) {
            atomicAdd(&g_pool[cur * 128 + tid], acc);
            if (tid == 0) atomicAdd(&g_cnt[cur], run);
            acc = 0.0f; run = 0; cur = gg;
        }
        acc += H[(size_t)n * 128 + tid];
        run++;
    }
    atomicAdd(&g_pool[cur * 128 + tid], acc);
    if (tid == 0) atomicAdd(&g_cnt[cur], run);
}

// ---------------- final linear ----------------------------------------------
__global__ void final_kernel(const float* __restrict__ lin_w,
                             const float* __restrict__ lin_b,
                             float* __restrict__ out)
{
    int t = blockIdx.x * blockDim.x + threadIdx.x;
    if (t >= N_GRAPHS * OUT_F) return;
    int gg = t >> 3, o = t & 7;
    float cval = fmaxf((float)g_cnt[gg], 1.0f);
    float invc = 1.0f / cval;
    float acc = 0.0f;
    for (int k = 0; k < 128; k++)
        acc = fmaf(g_pool[gg * 128 + k] * invc, lin_w[k * OUT_F + o], acc);
    out[t] = acc + lin_b[o];
}

// ---------------- driver -----------------------------------------------------
extern "C" void kernel_launch(void* const* d_in, const int* in_sizes, int n_in,
                              void* d_out, int out_size)
{
    const float* x      = (const float*)d_in[0];
    const void*  eidx   = d_in[1];
    const void*  batch  = d_in[3];
    const float* W[3]     = {(const float*)d_in[4],  (const float*)d_in[8],  (const float*)d_in[12]};
    const float* a_src[3] = {(const float*)d_in[5],  (const float*)d_in[9],  (const float*)d_in[13]};
    const float* a_dst[3] = {(const float*)d_in[6],  (const float*)d_in[10], (const float*)d_in[14]};
    const float* bias[3]  = {(const float*)d_in[7],  (const float*)d_in[11], (const float*)d_in[15]};
    const float* lin_w  = (const float*)d_in[16];
    const float* lin_b  = (const float*)d_in[17];
    float* out = (float*)d_out;

    // one-time resource setup (host objects only; no device memory)
    static cudaStream_t s2 = nullptr;
    static cudaEvent_t evFork = nullptr, evJoin = nullptr;
    if (s2 == nullptr) {
        cudaStreamCreateWithFlags(&s2, cudaStreamNonBlocking);
        cudaEventCreateWithFlags(&evFork, cudaEventDisableTiming);
        cudaEventCreateWithFlags(&evJoin, cudaEventDisableTiming);
    }

    const int E = N_EDGES;
    const int eb = (E + 255) / 256;
    const int nb = (N_NODES + 255) / 256;

    int* degp; cudaGetSymbolAddress((void**)&degp, g_deg);
    __half* hbuf; cudaGetSymbolAddress((void**)&hbuf, g_h);
    float* obuf;  cudaGetSymbolAddress((void**)&obuf, g_out);

    const int gemm_blocks = (N_NODES + BM - 1) / BM;
    const int warp_blocks = (N_NODES * 32 + 255) / 256;

    // fork: CSR build on s2, layer-0 GEMM (independent) on main stream
    cudaEventRecord(evFork, 0);
    cudaStreamWaitEvent(s2, evFork, 0);

    detect_kernel<<<1, 256, 0, s2>>>((const unsigned*)eidx);
    zero_i<<<nb, 256, 0, s2>>>(degp, N_NODES);
    hist_kernel<<<eb, 256, 0, s2>>>(eidx, E);
    scan1_kernel<<<N_SCAN_BLOCKS, 1024, 0, s2>>>();
    scan2_kernel<<<1, 64, 0, s2>>>();
    scan3_kernel<<<nb, 256, 0, s2>>>();
    scatter_kernel<<<eb, 256, 0, s2>>>(eidx, E);
    zero_pool_kernel<<<(N_GRAPHS * HID + 255) / 256, 256, 0, s2>>>();

    gemm_f16_kernel<<<gemm_blocks, 256>>>(x, W[0], hbuf, a_src[0], a_dst[0],
                                          N_NODES, IN_F);

    // join: aggregation needs both the CSR and alpha
    cudaEventRecord(evJoin, s2);
    cudaStreamWaitEvent(0, evJoin, 0);

    agg_kernel<<<warp_blocks, 256>>>(hbuf, bias[0], obuf, 1);

    for (int l = 1; l < 3; l++) {
        gemm_f16_kernel<<<gemm_blocks, 256>>>(obuf, W[l], hbuf, a_src[l], a_dst[l],
                                              N_NODES, HID);
        agg_kernel<<<warp_blocks, 256>>>(hbuf, bias[l], obuf, l == 2 ? 0 : 1);
    }

    pool_kernel<<<(N_NODES + NODES_PER_BLOCK - 1) / NODES_PER_BLOCK, 128>>>(obuf, batch);
    final_kernel<<<(N_GRAPHS * OUT_F + 255) / 256, 256>>>(lin_w, lin_b, out);
}